// round 14
// baseline (speedup 1.0000x reference)
#include <cuda_runtime.h>
#include <cstdint>

#define BB   8
#define NN   4096
#define KNN  10
#define HH   64

typedef unsigned long long ull;

// ---------------- scratch (device globals: no allocations allowed) ----------
__device__ float g_h1[BB * NN * HH];           // EdgeConv1 output
__device__ float g_uu[BB * NN * HH];           // h_i @ (W1b_top - W1b_bot) + b1b
__device__ float g_vv[BB * NN * HH];           // h_j @ W1b_bot
__device__ int   g_idx[BB * NN * KNN];         // knn indices (global node ids)
__device__ float g_sqm[BB * NN];               // GEMM-consistent squared norms
__device__ ull   g_h1T[BB * 32 * NN];          // transposed pairs: [b][kp][node]

// ---------------- f32x2 helpers ---------------------------------------------
__device__ __forceinline__ ull fma2(ull a, ull b, ull c) {
    ull d;
    asm("fma.rn.f32x2 %0, %1, %2, %3;" : "=l"(d) : "l"(a), "l"(b), "l"(c));
    return d;
}
__device__ __forceinline__ float red2(ull a) {
    unsigned lo, hi;
    asm("mov.b64 {%0, %1}, %2;" : "=r"(lo), "=r"(hi) : "l"(a));
    return __uint_as_float(lo) + __uint_as_float(hi);
}

// ---------------- top-k insertion (register-resident) ------------------------
#define TOPK_INIT(bd, bi)                                   \
    _Pragma("unroll")                                       \
    for (int p = 0; p < KNN; ++p) { bd[p] = 3.4e38f; bi[p] = 0x7fffffff; }

#define TOPK_TRY(bd, bi, d, j)                              \
    if ((d) < bd[KNN - 1]) {                                \
        bd[KNN - 1] = (d); bi[KNN - 1] = (j);               \
        _Pragma("unroll")                                   \
        for (int p = KNN - 1; p > 0; --p) {                 \
            if (bd[p] < bd[p - 1]) {                        \
                float tf = bd[p]; bd[p] = bd[p - 1]; bd[p - 1] = tf; \
                int   ti = bi[p]; bi[p] = bi[p - 1]; bi[p - 1] = ti; \
            }                                               \
        }                                                   \
    }

// lexicographic (d, idx) insertion for merging partial lists (matches top_k)
#define TOPK_TRY2(bd, bi, d, j)                                         \
    if ((d) < bd[KNN - 1] || ((d) == bd[KNN - 1] && (j) < bi[KNN - 1])) { \
        bd[KNN - 1] = (d); bi[KNN - 1] = (j);                           \
        _Pragma("unroll")                                               \
        for (int p = KNN - 1; p > 0; --p) {                             \
            if (bd[p] < bd[p - 1] ||                                    \
                (bd[p] == bd[p - 1] && bi[p] < bi[p - 1])) {            \
                float tf = bd[p]; bd[p] = bd[p - 1]; bd[p - 1] = tf;    \
                int   ti = bi[p]; bi[p] = bi[p - 1]; bi[p - 1] = ti;    \
            }                                                           \
        }                                                               \
    }

// =============================================================================
// Kernel 1: knn over 3-dim input x.  grid = 128 (16 CTAs/batch), block = 256.
// =============================================================================
__global__ void knn3_kernel(const float* __restrict__ x) {
    extern __shared__ float sm[];
    float* xs0 = sm;
    float* xs1 = sm + NN;
    float* xs2 = sm + 2 * NN;
    float* sq  = sm + 3 * NN;

    const int b    = blockIdx.x >> 4;
    const int qo   = (blockIdx.x & 15) * 256;
    const int base = b * NN;

    for (int t = threadIdx.x; t < NN; t += 256) {
        float a0 = x[(base + t) * 3 + 0];
        float a1 = x[(base + t) * 3 + 1];
        float a2 = x[(base + t) * 3 + 2];
        xs0[t] = a0; xs1[t] = a1; xs2[t] = a2;
        sq[t]  = fmaf(a2, a2, fmaf(a1, a1, a0 * a0));
    }
    __syncthreads();

    const int il  = qo + threadIdx.x;
    const float xi0 = xs0[il], xi1 = xs1[il], xi2 = xs2[il];
    const float sqi = sq[il];

    float bd[KNN]; int bi[KNN];
    TOPK_INIT(bd, bi);

    for (int j = 0; j < NN; ++j) {
        float dot = fmaf(xi2, xs2[j], fmaf(xi1, xs1[j], xi0 * xs0[j]));
        float d   = fmaf(-2.f, dot, sqi + sq[j]);
        TOPK_TRY(bd, bi, d, j);
    }

#pragma unroll
    for (int p = 0; p < KNN; ++p)
        g_idx[(size_t)(base + il) * KNN + p] = base + bi[p];
}

// =============================================================================
// Kernel 2: EdgeConv1 (C=3 -> 64 -> 64, max over k).  One warp per node.
// =============================================================================
__global__ void ec1_kernel(const float* __restrict__ x,
                           const float* __restrict__ W1,
                           const float* __restrict__ b1,
                           const float* __restrict__ W2,
                           const float* __restrict__ b2) {
    __shared__ float wd[3 * HH], wb[3 * HH];
    __shared__ float w2s[HH * HH];
    __shared__ float b1s[HH], b2s[HH];
    __shared__ __align__(16) float es[8][HH];

    const int tid = threadIdx.x;
    if (tid < 192) {
        float top = W1[tid], bot = W1[192 + tid];
        wd[tid] = top - bot;
        wb[tid] = bot;
    }
    if (tid < HH) { b1s[tid] = b1[tid]; b2s[tid] = b2[tid]; }
    for (int t = tid; t < HH * HH; t += 256) w2s[t] = W2[t];
    __syncthreads();

    const int w = tid >> 5, l = tid & 31;
    const int i = blockIdx.x * 8 + w;
    const int c0 = l, c1 = l + 32;

    const float xi0 = x[i * 3 + 0], xi1 = x[i * 3 + 1], xi2 = x[i * 3 + 2];
    const float u0 = b1s[c0] + xi0 * wd[c0] + xi1 * wd[64 + c0] + xi2 * wd[128 + c0];
    const float u1 = b1s[c1] + xi0 * wd[c1] + xi1 * wd[64 + c1] + xi2 * wd[128 + c1];

    float mx0 = -3.4e38f, mx1 = -3.4e38f;

    for (int kk = 0; kk < KNN; ++kk) {
        const int j = g_idx[(size_t)i * KNN + kk];
        const float xj0 = x[j * 3 + 0], xj1 = x[j * 3 + 1], xj2 = x[j * 3 + 2];
        float e0 = fmaxf(u0 + xj0 * wb[c0] + xj1 * wb[64 + c0] + xj2 * wb[128 + c0], 0.f);
        float e1 = fmaxf(u1 + xj0 * wb[c1] + xj1 * wb[64 + c1] + xj2 * wb[128 + c1], 0.f);
        __syncwarp();
        es[w][c0] = e0; es[w][c1] = e1;
        __syncwarp();

        float a0 = 0.f, a1 = 0.f;
#pragma unroll
        for (int c4 = 0; c4 < 16; ++c4) {
            float4 ev = ((const float4*)es[w])[c4];
            float2 r;
            r = ((const float2*)(w2s + (c4 * 4 + 0) * HH))[l];
            a0 = fmaf(ev.x, r.x, a0); a1 = fmaf(ev.x, r.y, a1);
            r = ((const float2*)(w2s + (c4 * 4 + 1) * HH))[l];
            a0 = fmaf(ev.y, r.x, a0); a1 = fmaf(ev.y, r.y, a1);
            r = ((const float2*)(w2s + (c4 * 4 + 2) * HH))[l];
            a0 = fmaf(ev.z, r.x, a0); a1 = fmaf(ev.z, r.y, a1);
            r = ((const float2*)(w2s + (c4 * 4 + 3) * HH))[l];
            a0 = fmaf(ev.w, r.x, a0); a1 = fmaf(ev.w, r.y, a1);
        }
        mx0 = fmaxf(mx0, a0); mx1 = fmaxf(mx1, a1);
    }

    float2 out = make_float2(mx0 + b2s[2 * l], mx1 + b2s[2 * l + 1]);
    ((float2*)(g_h1 + (size_t)i * HH))[l] = out;
}

// =============================================================================
// Kernel 2b: squared norms of h1 with EXACTLY the same fma2 chain the GEMM
// uses (single accumulator chain over 32 k-pairs, then lo+hi reduce), so the
// self-distance cancels to exactly 0.
// =============================================================================
__global__ void sqm_kernel() {
    const int i = blockIdx.x * 256 + threadIdx.x;      // node id
    const ull* h2 = (const ull*)(g_h1 + (size_t)i * HH);
    ull acc = 0ull;
#pragma unroll
    for (int kp = 0; kp < 32; ++kp) {
        ull v = h2[kp];
        acc = fma2(v, v, acc);
    }
    g_sqm[i] = red2(acc);
}

// =============================================================================
// Kernel 2c: global transpose of h1 into pair-major layout:
//   g_h1T[b][kp][node] = (h1[node][2kp], h1[node][2kp+1]) packed in one ull.
// Smem-tiled (pad stride 33 -> conflict-free), coalesced both directions.
// grid = 128, block = 256 (256 nodes per CTA).
// =============================================================================
__global__ void h1t_kernel() {
    extern __shared__ ull ts[];                 // [256][33]
    const int tid = threadIdx.x;
    const int n0  = blockIdx.x * 256;           // global node base
    const ull* src = (const ull*)g_h1 + (size_t)n0 * 32;

    for (int t = tid; t < 256 * 32; t += 256) {
        const int node = t >> 5, k = t & 31;
        ts[node * 33 + k] = src[t];             // coalesced LDG, conflict-free STS
    }
    __syncthreads();

    const int b  = n0 >> 12;
    const int nl = n0 & (NN - 1);
#pragma unroll
    for (int kp = 0; kp < 32; ++kp)             // conflict-free LDS, coalesced STG
        g_h1T[((size_t)(b * 32 + kp)) * NN + nl + tid] = ts[tid * 33 + kp];
}

// =============================================================================
// Kernel 3: per-node precompute for EdgeConv2.
// =============================================================================
__global__ void pre2_kernel(const float* __restrict__ W1,
                            const float* __restrict__ b1) {
    __shared__ float wdp[HH * HH], wbp[HH * HH], b1s[HH];
    __shared__ __align__(16) float hs[8][HH];

    for (int t = threadIdx.x; t < HH * HH; t += 256) {
        float top = W1[t], bot = W1[HH * HH + t];
        wdp[t] = top - bot;
        wbp[t] = bot;
    }
    if (threadIdx.x < HH) b1s[threadIdx.x] = b1[threadIdx.x];
    __syncthreads();

    const int w = threadIdx.x >> 5, l = threadIdx.x & 31;
    const int i = blockIdx.x * 8 + w;

    hs[w][l]      = g_h1[(size_t)i * HH + l];
    hs[w][l + 32] = g_h1[(size_t)i * HH + l + 32];
    __syncwarp();

    float u0 = 0.f, u1 = 0.f, v0 = 0.f, v1 = 0.f;
#pragma unroll
    for (int r4 = 0; r4 < 16; ++r4) {
        float4 hv = ((const float4*)hs[w])[r4];
        float2 d, b;
#define PRE_STEP(HV, ROW)                                              \
        d = ((const float2*)(wdp + (ROW) * HH))[l];                    \
        b = ((const float2*)(wbp + (ROW) * HH))[l];                    \
        u0 = fmaf(HV, d.x, u0); u1 = fmaf(HV, d.y, u1);                \
        v0 = fmaf(HV, b.x, v0); v1 = fmaf(HV, b.y, v1);
        PRE_STEP(hv.x, r4 * 4 + 0)
        PRE_STEP(hv.y, r4 * 4 + 1)
        PRE_STEP(hv.z, r4 * 4 + 2)
        PRE_STEP(hv.w, r4 * 4 + 3)
#undef PRE_STEP
    }

    ((float2*)(g_uu + (size_t)i * HH))[l] =
        make_float2(u0 + b1s[2 * l], u1 + b1s[2 * l + 1]);
    ((float2*)(g_vv + (size_t)i * HH))[l] = make_float2(v0, v1);
}

// =============================================================================
// Kernel 4: register-tile GEMM knn64, v2 (conflict-free).
// CTA = 64-query tile, grid = 8 * 64 = 512, block = 256 (16x16).
// Thread (tx,ty) owns q in {2ty, 2ty+1, 2ty+32, 2ty+33} x
//                     j in {2tx, 2tx+1, 2tx+32, 2tx+33};
// operands come from g_h1T (pre-transposed) so ALL smem traffic is
// consecutive-16B LDS.128 (2 wavefronts, zero conflicts).
//
// smem (floats): qT2 [32kp][64q] ull @0 (4096f), jT2 @4096 (4096f),
//                dist[64][65] @8192 (4160f), sqj @12352 (64f) = 49664 B.
// merge overlay after main loop re-uses qT2/jT2 space.
// =============================================================================
#define SMEM_K64 (12416 * 4)

__global__ void __launch_bounds__(256) knn64_gemm_kernel() {
    extern __shared__ float sm[];
    ull*   qT2  = (ull*)sm;                    // [32][64]
    ull*   jT2  = (ull*)(sm + 4096);           // [32][64]
    float* dist = sm + 8192;                   // [64][65]
    float* sqj  = sm + 12352;                  // [64]
    float* mld  = sm;                          // merge overlay: 2560 floats
    int*   mli  = (int*)(sm + 2560);           // merge overlay: 2560 ints

    const int tid  = threadIdx.x;
    const int tx   = tid & 15;
    const int ty   = tid >> 4;
    const int b    = blockIdx.x >> 6;          // 64 CTAs per batch
    const int qt   = blockIdx.x & 63;
    const int base = b * NN;
    const int q0   = qt * 64;

    // ---- load Q tile: straight row copies from g_h1T (coalesced) ----
    for (int t = tid; t < 2048; t += 256) {
        const int kp = t >> 6, ql = t & 63;
        qT2[t] = g_h1T[((size_t)(b * 32 + kp)) * NN + q0 + ql];
    }

    const int qrow0 = ty * 2;                  // q rows: qrow0, +1, +32, +33
    float sqa[4];
    sqa[0] = g_sqm[base + q0 + qrow0];
    sqa[1] = g_sqm[base + q0 + qrow0 + 1];
    sqa[2] = g_sqm[base + q0 + qrow0 + 32];
    sqa[3] = g_sqm[base + q0 + qrow0 + 33];

    float bd[KNN]; int bi[KNN];
    TOPK_INIT(bd, bi);

    const int qo = tid >> 2;          // query owned in scan phase (0..63)
    const int qr = tid & 3;           // quarter of j-range scanned

    for (int tile = 0; tile < NN / 64; ++tile) {
        const int j0 = tile * 64;
        __syncthreads();   // previous tile fully consumed

        for (int t = tid; t < 2048; t += 256) {
            const int kp = t >> 6, jl = t & 63;
            jT2[t] = g_h1T[((size_t)(b * 32 + kp)) * NN + j0 + jl];
        }
        if (tid < 64) sqj[tid] = g_sqm[base + j0 + tid];
        __syncthreads();

        // ---- 4x4 register-tile GEMM over 32 k-pairs ----
        ull acc[16];
#pragma unroll
        for (int t = 0; t < 16; ++t) acc[t] = 0ull;

#pragma unroll 4
        for (int kp = 0; kp < 32; ++kp) {
            // all four LDS.128: 16 consecutive 16B chunks across lanes
            ulonglong2 qa = *(const ulonglong2*)(qT2 + kp * 64 + ty * 2);
            ulonglong2 qb = *(const ulonglong2*)(qT2 + kp * 64 + 32 + ty * 2);
            ulonglong2 ja = *(const ulonglong2*)(jT2 + kp * 64 + tx * 2);
            ulonglong2 jb = *(const ulonglong2*)(jT2 + kp * 64 + 32 + tx * 2);
            ull qv[4] = {qa.x, qa.y, qb.x, qb.y};
            ull jv[4] = {ja.x, ja.y, jb.x, jb.y};
#pragma unroll
            for (int a = 0; a < 4; ++a)
#pragma unroll
                for (int c = 0; c < 4; ++c)
                    acc[a * 4 + c] = fma2(qv[a], jv[c], acc[a * 4 + c]);
        }

        // ---- epilogue: distances to smem ----
#pragma unroll
        for (int a = 0; a < 4; ++a) {
            const int qrw = qrow0 + (a & 1) + (a >> 1) * 32;
#pragma unroll
            for (int c = 0; c < 4; ++c) {
                const int jc = tx * 2 + (c & 1) + (c >> 1) * 32;
                float dot = red2(acc[a * 4 + c]);
                dist[qrw * 65 + jc] = fmaf(-2.f, dot, sqa[a] + sqj[jc]);
            }
        }
        __syncthreads();

        // ---- scan: 4 threads per query, contiguous 16-j ranges ----
#pragma unroll
        for (int jj = 0; jj < 16; ++jj) {
            float d = dist[qo * 65 + qr * 16 + jj];
            int   j = j0 + qr * 16 + jj;
            TOPK_TRY(bd, bi, d, j);
        }
    }

    // ---- final merge: 4 partial lists per query, lexicographic (d, idx) ----
    __syncthreads();
#pragma unroll
    for (int p = 0; p < KNN; ++p) {
        mld[(qo * 4 + qr) * KNN + p] = bd[p];
        mli[(qo * 4 + qr) * KNN + p] = bi[p];
    }
    __syncthreads();

    if (qr == 0) {
        float fd[KNN]; int fi[KNN];
        TOPK_INIT(fd, fi);
        for (int s = 0; s < 4; ++s) {
#pragma unroll
            for (int p = 0; p < KNN; ++p) {
                float d = mld[(qo * 4 + s) * KNN + p];
                int   i = mli[(qo * 4 + s) * KNN + p];
                TOPK_TRY2(fd, fi, d, i);
            }
        }
        const int qg = base + q0 + qo;
#pragma unroll
        for (int p = 0; p < KNN; ++p)
            g_idx[(size_t)qg * KNN + p] = base + fi[p];
    }
}

// =============================================================================
// Kernel 5: EdgeConv2 per-edge + max.  Writes final output.
// =============================================================================
__global__ void ec2_kernel(const float* __restrict__ W2,
                           const float* __restrict__ b2,
                           float* __restrict__ out) {
    __shared__ float w2s[HH * HH], b2s[HH];
    __shared__ __align__(16) float es[8][HH];

    for (int t = threadIdx.x; t < HH * HH; t += 256) w2s[t] = W2[t];
    if (threadIdx.x < HH) b2s[threadIdx.x] = b2[threadIdx.x];
    __syncthreads();

    const int w = threadIdx.x >> 5, l = threadIdx.x & 31;
    const int i = blockIdx.x * 8 + w;

    const float u0 = g_uu[(size_t)i * HH + l];
    const float u1 = g_uu[(size_t)i * HH + l + 32];

    float mx0 = -3.4e38f, mx1 = -3.4e38f;

    for (int kk = 0; kk < KNN; ++kk) {
        const int j = g_idx[(size_t)i * KNN + kk];
        float v0 = g_vv[(size_t)j * HH + l];
        float v1 = g_vv[(size_t)j * HH + l + 32];
        float e0 = fmaxf(u0 + v0, 0.f);
        float e1 = fmaxf(u1 + v1, 0.f);
        __syncwarp();
        es[w][l] = e0; es[w][l + 32] = e1;
        __syncwarp();

        float a0 = 0.f, a1 = 0.f;
#pragma unroll
        for (int c4 = 0; c4 < 16; ++c4) {
            float4 ev = ((const float4*)es[w])[c4];
            float2 r;
            r = ((const float2*)(w2s + (c4 * 4 + 0) * HH))[l];
            a0 = fmaf(ev.x, r.x, a0); a1 = fmaf(ev.x, r.y, a1);
            r = ((const float2*)(w2s + (c4 * 4 + 1) * HH))[l];
            a0 = fmaf(ev.y, r.x, a0); a1 = fmaf(ev.y, r.y, a1);
            r = ((const float2*)(w2s + (c4 * 4 + 2) * HH))[l];
            a0 = fmaf(ev.z, r.x, a0); a1 = fmaf(ev.z, r.y, a1);
            r = ((const float2*)(w2s + (c4 * 4 + 3) * HH))[l];
            a0 = fmaf(ev.w, r.x, a0); a1 = fmaf(ev.w, r.y, a1);
        }
        mx0 = fmaxf(mx0, a0); mx1 = fmaxf(mx1, a1);
    }

    ((float2*)(out + (size_t)i * HH))[l] =
        make_float2(mx0 + b2s[2 * l], mx1 + b2s[2 * l + 1]);
}

// =============================================================================
// launch
// =============================================================================
extern "C" void kernel_launch(void* const* d_in, const int* in_sizes, int n_in,
                              void* d_out, int out_size) {
    const float* x   = (const float*)d_in[0];
    // d_in[1] = batch (int64) — layout fixed (B=8 contiguous blocks of 4096)
    const float* W1a = (const float*)d_in[2];
    const float* b1a = (const float*)d_in[3];
    const float* W2a = (const float*)d_in[4];
    const float* b2a = (const float*)d_in[5];
    const float* W1b = (const float*)d_in[6];
    const float* b1b = (const float*)d_in[7];
    const float* W2b = (const float*)d_in[8];
    const float* b2b = (const float*)d_in[9];
    float* out = (float*)d_out;

    const int smem_knn3 = 4 * NN * (int)sizeof(float);   // 64 KB
    const int smem_h1t  = 256 * 33 * (int)sizeof(ull);   // ~67.5 KB
    cudaFuncSetAttribute(knn3_kernel,
                         cudaFuncAttributeMaxDynamicSharedMemorySize, smem_knn3);
    cudaFuncSetAttribute(h1t_kernel,
                         cudaFuncAttributeMaxDynamicSharedMemorySize, smem_h1t);
    cudaFuncSetAttribute(knn64_gemm_kernel,
                         cudaFuncAttributeMaxDynamicSharedMemorySize, SMEM_K64);

    knn3_kernel<<<128, 256, smem_knn3>>>(x);
    ec1_kernel<<<BB * NN / 8, 256>>>(x, W1a, b1a, W2a, b2a);
    h1t_kernel<<<BB * NN / 256, 256, smem_h1t>>>();
    sqm_kernel<<<BB * NN / 256, 256>>>();
    pre2_kernel<<<BB * NN / 8, 256>>>(W1b, b1b);
    knn64_gemm_kernel<<<BB * 64, 256, SMEM_K64>>>();
    ec2_kernel<<<BB * NN / 8, 256>>>(W2b, b2b, out);
}

// round 15
// speedup vs baseline: 1.1381x; 1.1381x over previous
#include <cuda_runtime.h>
#include <cstdint>

#define BB   8
#define NN   4096
#define KNN  10
#define HH   64

// knn64 tiling (round-9 measured config: 686us, regs=254)
#define TJ      512                 // j-tile held in smem
#define JSPLIT  2                   // j-range split across CTAs (knn3 AND knn64)
#define JRANGE  (NN / JSPLIT)       // 2048
#define QT      8                   // knn64 query tiles per batch (512 queries each)

typedef unsigned long long ull;

// ---------------- scratch (device globals: no allocations allowed) ----------
__device__ float g_h1[BB * NN * HH];           // EdgeConv1 output
__device__ float g_uu[BB * NN * HH];           // h_i @ (W1b_top - W1b_bot) + b1b
__device__ float g_vv[BB * NN * HH];           // h_j @ W1b_bot
__device__ int   g_idx[BB * NN * KNN];         // knn indices (global node ids)
__device__ float g_pd[BB * NN * JSPLIT * KNN]; // partial dists (knn3 then knn64)
__device__ int   g_pi[BB * NN * JSPLIT * KNN]; // partial idx (global ids)

// ---------------- f32x2 helpers ---------------------------------------------
__device__ __forceinline__ ull fma2(ull a, ull b, ull c) {
    ull d;
    asm("fma.rn.f32x2 %0, %1, %2, %3;" : "=l"(d) : "l"(a), "l"(b), "l"(c));
    return d;
}
__device__ __forceinline__ float red2(ull a) {
    unsigned lo, hi;
    asm("mov.b64 {%0, %1}, %2;" : "=r"(lo), "=r"(hi) : "l"(a));
    return __uint_as_float(lo) + __uint_as_float(hi);
}

// dot over 64 floats, both operands register arrays.  The EXACT same op
// sequence is used everywhere (sq_i, sq_j, dot_ij) so self-distances cancel
// to exactly 0.
__device__ __forceinline__ float dot64rr(const ulonglong2 (&a)[16],
                                         const ulonglong2 (&b)[16]) {
    ull acc0 = 0ull, acc1 = 0ull;
#pragma unroll
    for (int t = 0; t < 16; ++t) {
        acc0 = fma2(a[t].x, b[t].x, acc0);
        acc1 = fma2(a[t].y, b[t].y, acc1);
    }
    return red2(acc0) + red2(acc1);
}

// ---------------- top-k insertion (register-resident) ------------------------
#define TOPK_INIT(bd, bi)                                   \
    _Pragma("unroll")                                       \
    for (int p = 0; p < KNN; ++p) { bd[p] = 3.4e38f; bi[p] = 0x7fffffff; }

#define TOPK_TRY(bd, bi, d, j)                              \
    if ((d) < bd[KNN - 1]) {                                \
        bd[KNN - 1] = (d); bi[KNN - 1] = (j);               \
        _Pragma("unroll")                                   \
        for (int p = KNN - 1; p > 0; --p) {                 \
            if (bd[p] < bd[p - 1]) {                        \
                float tf = bd[p]; bd[p] = bd[p - 1]; bd[p - 1] = tf; \
                int   ti = bi[p]; bi[p] = bi[p - 1]; bi[p - 1] = ti; \
            }                                               \
        }                                                   \
    }

// lexicographic (d, idx) insertion for the merge kernel (matches lax.top_k)
#define TOPK_TRY2(bd, bi, d, j)                                         \
    if ((d) < bd[KNN - 1] || ((d) == bd[KNN - 1] && (j) < bi[KNN - 1])) { \
        bd[KNN - 1] = (d); bi[KNN - 1] = (j);                           \
        _Pragma("unroll")                                               \
        for (int p = KNN - 1; p > 0; --p) {                             \
            if (bd[p] < bd[p - 1] ||                                    \
                (bd[p] == bd[p - 1] && bi[p] < bi[p - 1])) {            \
                float tf = bd[p]; bd[p] = bd[p - 1]; bd[p - 1] = tf;    \
                int   ti = bi[p]; bi[p] = bi[p - 1]; bi[p - 1] = ti;    \
            }                                                           \
        }                                                               \
    }

// =============================================================================
// Kernel 1: knn over 3-dim input x, 2-way j-split.
// grid = 8 batches * 16 qtiles * 2 jsplits = 256 CTAs, block = 256.
// smem: j-half only (4 * 2048 floats = 32KB) -> multiple CTAs/SM.
// Queries read straight from gmem (3 floats each).
// =============================================================================
__global__ void knn3_kernel(const float* __restrict__ x) {
    extern __shared__ float sm[];
    float* xs0 = sm;
    float* xs1 = sm + JRANGE;
    float* xs2 = sm + 2 * JRANGE;
    float* sq  = sm + 3 * JRANGE;

    const int b     = blockIdx.x >> 5;            // 32 CTAs per batch
    const int qt    = (blockIdx.x >> 1) & 15;
    const int js    = blockIdx.x & 1;
    const int base  = b * NN;
    const int jbase = js * JRANGE;

    for (int t = threadIdx.x; t < JRANGE; t += 256) {
        const int n = base + jbase + t;
        float a0 = x[n * 3 + 0];
        float a1 = x[n * 3 + 1];
        float a2 = x[n * 3 + 2];
        xs0[t] = a0; xs1[t] = a1; xs2[t] = a2;
        sq[t]  = fmaf(a2, a2, fmaf(a1, a1, a0 * a0));
    }
    __syncthreads();

    const int il = qt * 256 + threadIdx.x;        // query local id
    const float xi0 = x[(base + il) * 3 + 0];
    const float xi1 = x[(base + il) * 3 + 1];
    const float xi2 = x[(base + il) * 3 + 2];
    const float sqi = fmaf(xi2, xi2, fmaf(xi1, xi1, xi0 * xi0));

    float bd[KNN]; int bi[KNN];
    TOPK_INIT(bd, bi);

    for (int j = 0; j < JRANGE; ++j) {
        float dot = fmaf(xi2, xs2[j], fmaf(xi1, xs1[j], xi0 * xs0[j]));
        float d   = fmaf(-2.f, dot, sqi + sq[j]);
        TOPK_TRY(bd, bi, d, jbase + j);
    }

#pragma unroll
    for (int p = 0; p < KNN; ++p) {
        g_pd[((size_t)(base + il) * JSPLIT + js) * KNN + p] = bd[p];
        g_pi[((size_t)(base + il) * JSPLIT + js) * KNN + p] = base + bi[p];
    }
}

// =============================================================================
// Merge kernel: JSPLIT partial top-10 lists per query, lexicographic (d,idx)
// tie-break (matches lax.top_k).  grid = 128, block = 256.
// Used after knn3 and after knn64.
// =============================================================================
__global__ void knn_merge_kernel() {
    const int q = blockIdx.x * 256 + threadIdx.x;   // 0..32767

    float bd[KNN]; int bi[KNN];
    TOPK_INIT(bd, bi);

    for (int s = 0; s < JSPLIT; ++s) {
#pragma unroll
        for (int p = 0; p < KNN; ++p) {
            float d = g_pd[((size_t)q * JSPLIT + s) * KNN + p];
            int   i = g_pi[((size_t)q * JSPLIT + s) * KNN + p];
            TOPK_TRY2(bd, bi, d, i);
        }
    }

#pragma unroll
    for (int p = 0; p < KNN; ++p)
        g_idx[(size_t)q * KNN + p] = bi[p];
}

// =============================================================================
// Kernel 2: EdgeConv1 (C=3 -> 64 -> 64, max over k).  One warp per node.
// =============================================================================
__global__ void ec1_kernel(const float* __restrict__ x,
                           const float* __restrict__ W1,
                           const float* __restrict__ b1,
                           const float* __restrict__ W2,
                           const float* __restrict__ b2) {
    __shared__ float wd[3 * HH], wb[3 * HH];
    __shared__ float w2s[HH * HH];
    __shared__ float b1s[HH], b2s[HH];
    __shared__ __align__(16) float es[8][HH];

    const int tid = threadIdx.x;
    if (tid < 192) {
        float top = W1[tid], bot = W1[192 + tid];
        wd[tid] = top - bot;
        wb[tid] = bot;
    }
    if (tid < HH) { b1s[tid] = b1[tid]; b2s[tid] = b2[tid]; }
    for (int t = tid; t < HH * HH; t += 256) w2s[t] = W2[t];
    __syncthreads();

    const int w = tid >> 5, l = tid & 31;
    const int i = blockIdx.x * 8 + w;
    const int c0 = l, c1 = l + 32;

    const float xi0 = x[i * 3 + 0], xi1 = x[i * 3 + 1], xi2 = x[i * 3 + 2];
    const float u0 = b1s[c0] + xi0 * wd[c0] + xi1 * wd[64 + c0] + xi2 * wd[128 + c0];
    const float u1 = b1s[c1] + xi0 * wd[c1] + xi1 * wd[64 + c1] + xi2 * wd[128 + c1];

    float mx0 = -3.4e38f, mx1 = -3.4e38f;

    for (int kk = 0; kk < KNN; ++kk) {
        const int j = g_idx[(size_t)i * KNN + kk];
        const float xj0 = x[j * 3 + 0], xj1 = x[j * 3 + 1], xj2 = x[j * 3 + 2];
        float e0 = fmaxf(u0 + xj0 * wb[c0] + xj1 * wb[64 + c0] + xj2 * wb[128 + c0], 0.f);
        float e1 = fmaxf(u1 + xj0 * wb[c1] + xj1 * wb[64 + c1] + xj2 * wb[128 + c1], 0.f);
        __syncwarp();
        es[w][c0] = e0; es[w][c1] = e1;
        __syncwarp();

        float a0 = 0.f, a1 = 0.f;
#pragma unroll
        for (int c4 = 0; c4 < 16; ++c4) {
            float4 ev = ((const float4*)es[w])[c4];
            float2 r;
            r = ((const float2*)(w2s + (c4 * 4 + 0) * HH))[l];
            a0 = fmaf(ev.x, r.x, a0); a1 = fmaf(ev.x, r.y, a1);
            r = ((const float2*)(w2s + (c4 * 4 + 1) * HH))[l];
            a0 = fmaf(ev.y, r.x, a0); a1 = fmaf(ev.y, r.y, a1);
            r = ((const float2*)(w2s + (c4 * 4 + 2) * HH))[l];
            a0 = fmaf(ev.z, r.x, a0); a1 = fmaf(ev.z, r.y, a1);
            r = ((const float2*)(w2s + (c4 * 4 + 3) * HH))[l];
            a0 = fmaf(ev.w, r.x, a0); a1 = fmaf(ev.w, r.y, a1);
        }
        mx0 = fmaxf(mx0, a0); mx1 = fmaxf(mx1, a1);
    }

    float2 out = make_float2(mx0 + b2s[2 * l], mx1 + b2s[2 * l + 1]);
    ((float2*)(g_h1 + (size_t)i * HH))[l] = out;
}

// =============================================================================
// Kernel 3: per-node precompute for EdgeConv2.
// =============================================================================
__global__ void pre2_kernel(const float* __restrict__ W1,
                            const float* __restrict__ b1) {
    __shared__ float wdp[HH * HH], wbp[HH * HH], b1s[HH];
    __shared__ __align__(16) float hs[8][HH];

    for (int t = threadIdx.x; t < HH * HH; t += 256) {
        float top = W1[t], bot = W1[HH * HH + t];
        wdp[t] = top - bot;
        wbp[t] = bot;
    }
    if (threadIdx.x < HH) b1s[threadIdx.x] = b1[threadIdx.x];
    __syncthreads();

    const int w = threadIdx.x >> 5, l = threadIdx.x & 31;
    const int i = blockIdx.x * 8 + w;

    hs[w][l]      = g_h1[(size_t)i * HH + l];
    hs[w][l + 32] = g_h1[(size_t)i * HH + l + 32];
    __syncwarp();

    float u0 = 0.f, u1 = 0.f, v0 = 0.f, v1 = 0.f;
#pragma unroll
    for (int r4 = 0; r4 < 16; ++r4) {
        float4 hv = ((const float4*)hs[w])[r4];
        float2 d, b;
#define PRE_STEP(HV, ROW)                                              \
        d = ((const float2*)(wdp + (ROW) * HH))[l];                    \
        b = ((const float2*)(wbp + (ROW) * HH))[l];                    \
        u0 = fmaf(HV, d.x, u0); u1 = fmaf(HV, d.y, u1);                \
        v0 = fmaf(HV, b.x, v0); v1 = fmaf(HV, b.y, v1);
        PRE_STEP(hv.x, r4 * 4 + 0)
        PRE_STEP(hv.y, r4 * 4 + 1)
        PRE_STEP(hv.z, r4 * 4 + 2)
        PRE_STEP(hv.w, r4 * 4 + 3)
#undef PRE_STEP
    }

    ((float2*)(g_uu + (size_t)i * HH))[l] =
        make_float2(u0 + b1s[2 * l], u1 + b1s[2 * l + 1]);
    ((float2*)(g_vv + (size_t)i * HH))[l] = make_float2(v0, v1);
}

// =============================================================================
// Kernel 4: knn over 64-dim h1 — round-9 measured config, VERBATIM.
// Q=2 queries/thread, 2-way j-split, TJ=512, grid = 128 CTAs, block = 256.
// =============================================================================
__global__ void __launch_bounds__(256) knn64_kernel() {
    extern __shared__ float sm[];
    float* tilev = sm;                 // [TJ][HH]
    float* sqt   = sm + TJ * HH;       // [TJ]

    const int cta  = blockIdx.x;
    const int b    = cta >> 4;                 // 16 CTAs per batch
    const int qt   = (cta >> 1) & (QT - 1);
    const int js   = cta & (JSPLIT - 1);
    const int base = b * NN;
    const int q0g  = base + qt * 512 + threadIdx.x;   // global node id, query 0
    const int q1g  = q0g + 256;                        // query 1
    const int jbase = js * JRANGE;

    ulonglong2 qa[16], qb[16];
    {
        const ulonglong2* pa = (const ulonglong2*)(g_h1 + (size_t)q0g * HH);
        const ulonglong2* pb = (const ulonglong2*)(g_h1 + (size_t)q1g * HH);
#pragma unroll
        for (int t = 0; t < 16; ++t) { qa[t] = pa[t]; qb[t] = pb[t]; }
    }
    const float sqa = dot64rr(qa, qa);
    const float sqb = dot64rr(qb, qb);

    float bda[KNN], bdb[KNN]; int bia[KNN], bib[KNN];
    TOPK_INIT(bda, bia);
    TOPK_INIT(bdb, bib);

    for (int tile = 0; tile < JRANGE / TJ; ++tile) {
        __syncthreads();   // protect reads of the previous tile
        {
            const float4* src =
                (const float4*)(g_h1 + ((size_t)base + jbase + tile * TJ) * HH);
            float4* dst = (float4*)tilev;
#pragma unroll
            for (int t = 0; t < TJ * HH / 4 / 256; ++t)
                dst[t * 256 + threadIdx.x] = src[t * 256 + threadIdx.x];
        }
        __syncthreads();
        {   // per-row squared norms: rows tid and tid+256 (TJ = 512)
#pragma unroll
            for (int rr = 0; rr < TJ / 256; ++rr) {
                const int row = rr * 256 + threadIdx.x;
                ulonglong2 r[16];
                const ulonglong2* rp = (const ulonglong2*)(tilev + row * HH);
#pragma unroll
                for (int t = 0; t < 16; ++t) r[t] = rp[t];
                sqt[row] = dot64rr(r, r);
            }
        }
        __syncthreads();

        for (int jj = 0; jj < TJ; ++jj) {
            const ulonglong2* rp = (const ulonglong2*)(tilev + jj * HH);
            ull a0 = 0ull, a1 = 0ull, c0 = 0ull, c1 = 0ull;
#pragma unroll
            for (int t = 0; t < 16; ++t) {
                ulonglong2 rv = rp[t];
                a0 = fma2(qa[t].x, rv.x, a0);
                a1 = fma2(qa[t].y, rv.y, a1);
                c0 = fma2(qb[t].x, rv.x, c0);
                c1 = fma2(qb[t].y, rv.y, c1);
            }
            float dota = red2(a0) + red2(a1);
            float dotb = red2(c0) + red2(c1);
            float sj = sqt[jj];
            float da = fmaf(-2.f, dota, sqa + sj);
            float db = fmaf(-2.f, dotb, sqb + sj);
            int   j  = jbase + tile * TJ + jj;
            TOPK_TRY(bda, bia, da, j);
            TOPK_TRY(bdb, bib, db, j);
        }
    }

#pragma unroll
    for (int p = 0; p < KNN; ++p) {
        g_pd[((size_t)q0g * JSPLIT + js) * KNN + p] = bda[p];
        g_pi[((size_t)q0g * JSPLIT + js) * KNN + p] = base + bia[p];
        g_pd[((size_t)q1g * JSPLIT + js) * KNN + p] = bdb[p];
        g_pi[((size_t)q1g * JSPLIT + js) * KNN + p] = base + bib[p];
    }
}

// =============================================================================
// Kernel 5: EdgeConv2 per-edge + max.  Writes final output.
// =============================================================================
__global__ void ec2_kernel(const float* __restrict__ W2,
                           const float* __restrict__ b2,
                           float* __restrict__ out) {
    __shared__ float w2s[HH * HH], b2s[HH];
    __shared__ __align__(16) float es[8][HH];

    for (int t = threadIdx.x; t < HH * HH; t += 256) w2s[t] = W2[t];
    if (threadIdx.x < HH) b2s[threadIdx.x] = b2[threadIdx.x];
    __syncthreads();

    const int w = threadIdx.x >> 5, l = threadIdx.x & 31;
    const int i = blockIdx.x * 8 + w;

    const float u0 = g_uu[(size_t)i * HH + l];
    const float u1 = g_uu[(size_t)i * HH + l + 32];

    float mx0 = -3.4e38f, mx1 = -3.4e38f;

    for (int kk = 0; kk < KNN; ++kk) {
        const int j = g_idx[(size_t)i * KNN + kk];
        float v0 = g_vv[(size_t)j * HH + l];
        float v1 = g_vv[(size_t)j * HH + l + 32];
        float e0 = fmaxf(u0 + v0, 0.f);
        float e1 = fmaxf(u1 + v1, 0.f);
        __syncwarp();
        es[w][l] = e0; es[w][l + 32] = e1;
        __syncwarp();

        float a0 = 0.f, a1 = 0.f;
#pragma unroll
        for (int c4 = 0; c4 < 16; ++c4) {
            float4 ev = ((const float4*)es[w])[c4];
            float2 r;
            r = ((const float2*)(w2s + (c4 * 4 + 0) * HH))[l];
            a0 = fmaf(ev.x, r.x, a0); a1 = fmaf(ev.x, r.y, a1);
            r = ((const float2*)(w2s + (c4 * 4 + 1) * HH))[l];
            a0 = fmaf(ev.y, r.x, a0); a1 = fmaf(ev.y, r.y, a1);
            r = ((const float2*)(w2s + (c4 * 4 + 2) * HH))[l];
            a0 = fmaf(ev.z, r.x, a0); a1 = fmaf(ev.z, r.y, a1);
            r = ((const float2*)(w2s + (c4 * 4 + 3) * HH))[l];
            a0 = fmaf(ev.w, r.x, a0); a1 = fmaf(ev.w, r.y, a1);
        }
        mx0 = fmaxf(mx0, a0); mx1 = fmaxf(mx1, a1);
    }

    ((float2*)(out + (size_t)i * HH))[l] =
        make_float2(mx0 + b2s[2 * l], mx1 + b2s[2 * l + 1]);
}

// =============================================================================
// launch — ordered so the 4th launch (ncu's capture slot) is knn64.
// Dependencies: knn3->merge->ec1->{knn64, pre2}; {merge64, pre2}->ec2.
// =============================================================================
extern "C" void kernel_launch(void* const* d_in, const int* in_sizes, int n_in,
                              void* d_out, int out_size) {
    const float* x   = (const float*)d_in[0];
    // d_in[1] = batch (int64) — layout fixed (B=8 contiguous blocks of 4096)
    const float* W1a = (const float*)d_in[2];
    const float* b1a = (const float*)d_in[3];
    const float* W2a = (const float*)d_in[4];
    const float* b2a = (const float*)d_in[5];
    const float* W1b = (const float*)d_in[6];
    const float* b1b = (const float*)d_in[7];
    const float* W2b = (const float*)d_in[8];
    const float* b2b = (const float*)d_in[9];
    float* out = (float*)d_out;

    const int smem_knn3  = 4 * JRANGE * (int)sizeof(float);       // 32 KB
    const int smem_knn64 = (TJ * HH + TJ) * (int)sizeof(float);   // ~130 KB
    cudaFuncSetAttribute(knn3_kernel,
                         cudaFuncAttributeMaxDynamicSharedMemorySize, smem_knn3);
    cudaFuncSetAttribute(knn64_kernel,
                         cudaFuncAttributeMaxDynamicSharedMemorySize, smem_knn64);

    knn3_kernel<<<BB * 16 * JSPLIT, 256, smem_knn3>>>(x);   // 1
    knn_merge_kernel<<<BB * NN / 256, 256>>>();             // 2
    ec1_kernel<<<BB * NN / 8, 256>>>(x, W1a, b1a, W2a, b2a);// 3
    knn64_kernel<<<BB * QT * JSPLIT, 256, smem_knn64>>>();  // 4  <- profiled
    pre2_kernel<<<BB * NN / 8, 256>>>(W1b, b1b);            // 5 (indep of 4)
    knn_merge_kernel<<<BB * NN / 256, 256>>>();             // 6
    ec2_kernel<<<BB * NN / 8, 256>>>(W2b, b2b, out);        // 7
}

// round 16
// speedup vs baseline: 1.1721x; 1.0298x over previous
#include <cuda_runtime.h>
#include <cstdint>

#define BB   8
#define NN   4096
#define KNN  10
#define HH   64

// knn64 tiling (round-9/15 measured config)
#define TJ      512                 // j-tile held in smem
#define JSPLIT  2                   // j-range split across CTAs (knn3 AND knn64)
#define JRANGE  (NN / JSPLIT)       // 2048
#define QT      8                   // knn64 query tiles per batch (512 queries each)

typedef unsigned long long ull;

// ---------------- scratch (device globals: no allocations allowed) ----------
__device__ float g_h1[BB * NN * HH];           // EdgeConv1 output
__device__ float g_uu[BB * NN * HH];           // h_i @ (W1b_top - W1b_bot) + b1b
__device__ float g_vv[BB * NN * HH];           // h_j @ W1b_bot
__device__ int   g_idx[BB * NN * KNN];         // knn indices (global node ids)
__device__ float g_pd[BB * NN * JSPLIT * KNN]; // partial dists (knn3 then knn64)
__device__ int   g_pi[BB * NN * JSPLIT * KNN]; // partial idx (global ids)

// ---------------- f32x2 helpers ---------------------------------------------
__device__ __forceinline__ ull fma2(ull a, ull b, ull c) {
    ull d;
    asm("fma.rn.f32x2 %0, %1, %2, %3;" : "=l"(d) : "l"(a), "l"(b), "l"(c));
    return d;
}
__device__ __forceinline__ float red2(ull a) {
    unsigned lo, hi;
    asm("mov.b64 {%0, %1}, %2;" : "=r"(lo), "=r"(hi) : "l"(a));
    return __uint_as_float(lo) + __uint_as_float(hi);
}

// dot over 64 floats, both operands register arrays.  The EXACT same op
// sequence is used everywhere (sq_i, sq_j, dot_ij) so self-distances cancel
// to exactly 0.
__device__ __forceinline__ float dot64rr(const ulonglong2 (&a)[16],
                                         const ulonglong2 (&b)[16]) {
    ull acc0 = 0ull, acc1 = 0ull;
#pragma unroll
    for (int t = 0; t < 16; ++t) {
        acc0 = fma2(a[t].x, b[t].x, acc0);
        acc1 = fma2(a[t].y, b[t].y, acc1);
    }
    return red2(acc0) + red2(acc1);
}

// ---------------- top-k insertion (register-resident) ------------------------
#define TOPK_INIT(bd, bi)                                   \
    _Pragma("unroll")                                       \
    for (int p = 0; p < KNN; ++p) { bd[p] = 3.4e38f; bi[p] = 0x7fffffff; }

#define TOPK_TRY(bd, bi, d, j)                              \
    if ((d) < bd[KNN - 1]) {                                \
        bd[KNN - 1] = (d); bi[KNN - 1] = (j);               \
        _Pragma("unroll")                                   \
        for (int p = KNN - 1; p > 0; --p) {                 \
            if (bd[p] < bd[p - 1]) {                        \
                float tf = bd[p]; bd[p] = bd[p - 1]; bd[p - 1] = tf; \
                int   ti = bi[p]; bi[p] = bi[p - 1]; bi[p - 1] = ti; \
            }                                               \
        }                                                   \
    }

// lexicographic (d, idx) insertion for the merge kernel (matches lax.top_k)
#define TOPK_TRY2(bd, bi, d, j)                                         \
    if ((d) < bd[KNN - 1] || ((d) == bd[KNN - 1] && (j) < bi[KNN - 1])) { \
        bd[KNN - 1] = (d); bi[KNN - 1] = (j);                           \
        _Pragma("unroll")                                               \
        for (int p = KNN - 1; p > 0; --p) {                             \
            if (bd[p] < bd[p - 1] ||                                    \
                (bd[p] == bd[p - 1] && bi[p] < bi[p - 1])) {            \
                float tf = bd[p]; bd[p] = bd[p - 1]; bd[p - 1] = tf;    \
                int   ti = bi[p]; bi[p] = bi[p - 1]; bi[p - 1] = ti;    \
            }                                                           \
        }                                                               \
    }

// =============================================================================
// Kernel 1: knn over 3-dim input x, 2-way j-split.
// grid = 8 batches * 16 qtiles * 2 jsplits = 256 CTAs, block = 256.
// =============================================================================
__global__ void knn3_kernel(const float* __restrict__ x) {
    extern __shared__ float sm[];
    float* xs0 = sm;
    float* xs1 = sm + JRANGE;
    float* xs2 = sm + 2 * JRANGE;
    float* sq  = sm + 3 * JRANGE;

    const int b     = blockIdx.x >> 5;            // 32 CTAs per batch
    const int qt    = (blockIdx.x >> 1) & 15;
    const int js    = blockIdx.x & 1;
    const int base  = b * NN;
    const int jbase = js * JRANGE;

    for (int t = threadIdx.x; t < JRANGE; t += 256) {
        const int n = base + jbase + t;
        float a0 = x[n * 3 + 0];
        float a1 = x[n * 3 + 1];
        float a2 = x[n * 3 + 2];
        xs0[t] = a0; xs1[t] = a1; xs2[t] = a2;
        sq[t]  = fmaf(a2, a2, fmaf(a1, a1, a0 * a0));
    }
    __syncthreads();

    const int il = qt * 256 + threadIdx.x;        // query local id
    const float xi0 = x[(base + il) * 3 + 0];
    const float xi1 = x[(base + il) * 3 + 1];
    const float xi2 = x[(base + il) * 3 + 2];
    const float sqi = fmaf(xi2, xi2, fmaf(xi1, xi1, xi0 * xi0));

    float bd[KNN]; int bi[KNN];
    TOPK_INIT(bd, bi);

    for (int j = 0; j < JRANGE; ++j) {
        float dot = fmaf(xi2, xs2[j], fmaf(xi1, xs1[j], xi0 * xs0[j]));
        float d   = fmaf(-2.f, dot, sqi + sq[j]);
        TOPK_TRY(bd, bi, d, jbase + j);
    }

#pragma unroll
    for (int p = 0; p < KNN; ++p) {
        g_pd[((size_t)(base + il) * JSPLIT + js) * KNN + p] = bd[p];
        g_pi[((size_t)(base + il) * JSPLIT + js) * KNN + p] = base + bi[p];
    }
}

// =============================================================================
// Merge kernel: JSPLIT partial top-10 lists per query, lexicographic (d,idx)
// tie-break (matches lax.top_k).  grid = 128, block = 256.
// =============================================================================
__global__ void knn_merge_kernel() {
    const int q = blockIdx.x * 256 + threadIdx.x;   // 0..32767

    float bd[KNN]; int bi[KNN];
    TOPK_INIT(bd, bi);

    for (int s = 0; s < JSPLIT; ++s) {
#pragma unroll
        for (int p = 0; p < KNN; ++p) {
            float d = g_pd[((size_t)q * JSPLIT + s) * KNN + p];
            int   i = g_pi[((size_t)q * JSPLIT + s) * KNN + p];
            TOPK_TRY2(bd, bi, d, i);
        }
    }

#pragma unroll
    for (int p = 0; p < KNN; ++p)
        g_idx[(size_t)q * KNN + p] = bi[p];
}

// =============================================================================
// Kernel 2: EdgeConv1 (C=3 -> 64 -> 64, max over k).  One warp per node.
// =============================================================================
__global__ void ec1_kernel(const float* __restrict__ x,
                           const float* __restrict__ W1,
                           const float* __restrict__ b1,
                           const float* __restrict__ W2,
                           const float* __restrict__ b2) {
    __shared__ float wd[3 * HH], wb[3 * HH];
    __shared__ float w2s[HH * HH];
    __shared__ float b1s[HH], b2s[HH];
    __shared__ __align__(16) float es[8][HH];

    const int tid = threadIdx.x;
    if (tid < 192) {
        float top = W1[tid], bot = W1[192 + tid];
        wd[tid] = top - bot;
        wb[tid] = bot;
    }
    if (tid < HH) { b1s[tid] = b1[tid]; b2s[tid] = b2[tid]; }
    for (int t = tid; t < HH * HH; t += 256) w2s[t] = W2[t];
    __syncthreads();

    const int w = tid >> 5, l = tid & 31;
    const int i = blockIdx.x * 8 + w;
    const int c0 = l, c1 = l + 32;

    const float xi0 = x[i * 3 + 0], xi1 = x[i * 3 + 1], xi2 = x[i * 3 + 2];
    const float u0 = b1s[c0] + xi0 * wd[c0] + xi1 * wd[64 + c0] + xi2 * wd[128 + c0];
    const float u1 = b1s[c1] + xi0 * wd[c1] + xi1 * wd[64 + c1] + xi2 * wd[128 + c1];

    float mx0 = -3.4e38f, mx1 = -3.4e38f;

    for (int kk = 0; kk < KNN; ++kk) {
        const int j = g_idx[(size_t)i * KNN + kk];
        const float xj0 = x[j * 3 + 0], xj1 = x[j * 3 + 1], xj2 = x[j * 3 + 2];
        float e0 = fmaxf(u0 + xj0 * wb[c0] + xj1 * wb[64 + c0] + xj2 * wb[128 + c0], 0.f);
        float e1 = fmaxf(u1 + xj0 * wb[c1] + xj1 * wb[64 + c1] + xj2 * wb[128 + c1], 0.f);
        __syncwarp();
        es[w][c0] = e0; es[w][c1] = e1;
        __syncwarp();

        float a0 = 0.f, a1 = 0.f;
#pragma unroll
        for (int c4 = 0; c4 < 16; ++c4) {
            float4 ev = ((const float4*)es[w])[c4];
            float2 r;
            r = ((const float2*)(w2s + (c4 * 4 + 0) * HH))[l];
            a0 = fmaf(ev.x, r.x, a0); a1 = fmaf(ev.x, r.y, a1);
            r = ((const float2*)(w2s + (c4 * 4 + 1) * HH))[l];
            a0 = fmaf(ev.y, r.x, a0); a1 = fmaf(ev.y, r.y, a1);
            r = ((const float2*)(w2s + (c4 * 4 + 2) * HH))[l];
            a0 = fmaf(ev.z, r.x, a0); a1 = fmaf(ev.z, r.y, a1);
            r = ((const float2*)(w2s + (c4 * 4 + 3) * HH))[l];
            a0 = fmaf(ev.w, r.x, a0); a1 = fmaf(ev.w, r.y, a1);
        }
        mx0 = fmaxf(mx0, a0); mx1 = fmaxf(mx1, a1);
    }

    float2 out = make_float2(mx0 + b2s[2 * l], mx1 + b2s[2 * l + 1]);
    ((float2*)(g_h1 + (size_t)i * HH))[l] = out;
}

// =============================================================================
// Kernel 3: per-node precompute for EdgeConv2.
// =============================================================================
__global__ void pre2_kernel(const float* __restrict__ W1,
                            const float* __restrict__ b1) {
    __shared__ float wdp[HH * HH], wbp[HH * HH], b1s[HH];
    __shared__ __align__(16) float hs[8][HH];

    for (int t = threadIdx.x; t < HH * HH; t += 256) {
        float top = W1[t], bot = W1[HH * HH + t];
        wdp[t] = top - bot;
        wbp[t] = bot;
    }
    if (threadIdx.x < HH) b1s[threadIdx.x] = b1[threadIdx.x];
    __syncthreads();

    const int w = threadIdx.x >> 5, l = threadIdx.x & 31;
    const int i = blockIdx.x * 8 + w;

    hs[w][l]      = g_h1[(size_t)i * HH + l];
    hs[w][l + 32] = g_h1[(size_t)i * HH + l + 32];
    __syncwarp();

    float u0 = 0.f, u1 = 0.f, v0 = 0.f, v1 = 0.f;
#pragma unroll
    for (int r4 = 0; r4 < 16; ++r4) {
        float4 hv = ((const float4*)hs[w])[r4];
        float2 d, b;
#define PRE_STEP(HV, ROW)                                              \
        d = ((const float2*)(wdp + (ROW) * HH))[l];                    \
        b = ((const float2*)(wbp + (ROW) * HH))[l];                    \
        u0 = fmaf(HV, d.x, u0); u1 = fmaf(HV, d.y, u1);                \
        v0 = fmaf(HV, b.x, v0); v1 = fmaf(HV, b.y, v1);
        PRE_STEP(hv.x, r4 * 4 + 0)
        PRE_STEP(hv.y, r4 * 4 + 1)
        PRE_STEP(hv.z, r4 * 4 + 2)
        PRE_STEP(hv.w, r4 * 4 + 3)
#undef PRE_STEP
    }

    ((float2*)(g_uu + (size_t)i * HH))[l] =
        make_float2(u0 + b1s[2 * l], u1 + b1s[2 * l + 1]);
    ((float2*)(g_vv + (size_t)i * HH))[l] = make_float2(v0, v1);
}

// =============================================================================
// Kernel 4: knn over 64-dim h1 — round-9/15 config with the jj loop manually
// unrolled x2 (interleaved chains + tails).  Arithmetic per (q,j) pair is
// bit-identical to round 15.
// Q=2 queries/thread, 2-way j-split, TJ=512, grid = 128 CTAs, block = 256.
// =============================================================================
__global__ void __launch_bounds__(256) knn64_kernel() {
    extern __shared__ float sm[];
    float* tilev = sm;                 // [TJ][HH]
    float* sqt   = sm + TJ * HH;       // [TJ]

    const int cta  = blockIdx.x;
    const int b    = cta >> 4;                 // 16 CTAs per batch
    const int qt   = (cta >> 1) & (QT - 1);
    const int js   = cta & (JSPLIT - 1);
    const int base = b * NN;
    const int q0g  = base + qt * 512 + threadIdx.x;   // global node id, query 0
    const int q1g  = q0g + 256;                        // query 1
    const int jbase = js * JRANGE;

    ulonglong2 qa[16], qb[16];
    {
        const ulonglong2* pa = (const ulonglong2*)(g_h1 + (size_t)q0g * HH);
        const ulonglong2* pb = (const ulonglong2*)(g_h1 + (size_t)q1g * HH);
#pragma unroll
        for (int t = 0; t < 16; ++t) { qa[t] = pa[t]; qb[t] = pb[t]; }
    }
    const float sqa = dot64rr(qa, qa);
    const float sqb = dot64rr(qb, qb);

    float bda[KNN], bdb[KNN]; int bia[KNN], bib[KNN];
    TOPK_INIT(bda, bia);
    TOPK_INIT(bdb, bib);

    for (int tile = 0; tile < JRANGE / TJ; ++tile) {
        __syncthreads();   // protect reads of the previous tile
        {
            const float4* src =
                (const float4*)(g_h1 + ((size_t)base + jbase + tile * TJ) * HH);
            float4* dst = (float4*)tilev;
#pragma unroll
            for (int t = 0; t < TJ * HH / 4 / 256; ++t)
                dst[t * 256 + threadIdx.x] = src[t * 256 + threadIdx.x];
        }
        __syncthreads();
        {   // per-row squared norms: rows tid and tid+256 (TJ = 512)
#pragma unroll
            for (int rr = 0; rr < TJ / 256; ++rr) {
                const int row = rr * 256 + threadIdx.x;
                ulonglong2 r[16];
                const ulonglong2* rp = (const ulonglong2*)(tilev + row * HH);
#pragma unroll
                for (int t = 0; t < 16; ++t) r[t] = rp[t];
                sqt[row] = dot64rr(r, r);
            }
        }
        __syncthreads();

        // jj loop unrolled x2: two j-rows in flight, 8 independent fma2
        // chains, tails interleaved so each hides under the other's math.
        for (int jj = 0; jj < TJ; jj += 2) {
            const ulonglong2* rp0 = (const ulonglong2*)(tilev + jj * HH);
            const ulonglong2* rp1 = (const ulonglong2*)(tilev + jj * HH + HH);
            ull a0 = 0ull, a1 = 0ull, c0 = 0ull, c1 = 0ull;   // j = jj
            ull e0 = 0ull, e1 = 0ull, f0 = 0ull, f1 = 0ull;   // j = jj+1
#pragma unroll
            for (int t = 0; t < 16; ++t) {
                ulonglong2 rv0 = rp0[t];
                ulonglong2 rv1 = rp1[t];
                a0 = fma2(qa[t].x, rv0.x, a0);
                a1 = fma2(qa[t].y, rv0.y, a1);
                c0 = fma2(qb[t].x, rv0.x, c0);
                c1 = fma2(qb[t].y, rv0.y, c1);
                e0 = fma2(qa[t].x, rv1.x, e0);
                e1 = fma2(qa[t].y, rv1.y, e1);
                f0 = fma2(qb[t].x, rv1.x, f0);
                f1 = fma2(qb[t].y, rv1.y, f1);
            }
            float dota0 = red2(a0) + red2(a1);
            float dotb0 = red2(c0) + red2(c1);
            float dota1 = red2(e0) + red2(e1);
            float dotb1 = red2(f0) + red2(f1);
            float sj0 = sqt[jj];
            float sj1 = sqt[jj + 1];
            float da0 = fmaf(-2.f, dota0, sqa + sj0);
            float db0 = fmaf(-2.f, dotb0, sqb + sj0);
            float da1 = fmaf(-2.f, dota1, sqa + sj1);
            float db1 = fmaf(-2.f, dotb1, sqb + sj1);
            const int j0 = jbase + tile * TJ + jj;
            TOPK_TRY(bda, bia, da0, j0);
            TOPK_TRY(bdb, bib, db0, j0);
            TOPK_TRY(bda, bia, da1, j0 + 1);
            TOPK_TRY(bdb, bib, db1, j0 + 1);
        }
    }

#pragma unroll
    for (int p = 0; p < KNN; ++p) {
        g_pd[((size_t)q0g * JSPLIT + js) * KNN + p] = bda[p];
        g_pi[((size_t)q0g * JSPLIT + js) * KNN + p] = base + bia[p];
        g_pd[((size_t)q1g * JSPLIT + js) * KNN + p] = bdb[p];
        g_pi[((size_t)q1g * JSPLIT + js) * KNN + p] = base + bib[p];
    }
}

// =============================================================================
// Kernel 5: EdgeConv2 per-edge + max.  Writes final output.
// =============================================================================
__global__ void ec2_kernel(const float* __restrict__ W2,
                           const float* __restrict__ b2,
                           float* __restrict__ out) {
    __shared__ float w2s[HH * HH], b2s[HH];
    __shared__ __align__(16) float es[8][HH];

    for (int t = threadIdx.x; t < HH * HH; t += 256) w2s[t] = W2[t];
    if (threadIdx.x < HH) b2s[threadIdx.x] = b2[threadIdx.x];
    __syncthreads();

    const int w = threadIdx.x >> 5, l = threadIdx.x & 31;
    const int i = blockIdx.x * 8 + w;

    const float u0 = g_uu[(size_t)i * HH + l];
    const float u1 = g_uu[(size_t)i * HH + l + 32];

    float mx0 = -3.4e38f, mx1 = -3.4e38f;

    for (int kk = 0; kk < KNN; ++kk) {
        const int j = g_idx[(size_t)i * KNN + kk];
        float v0 = g_vv[(size_t)j * HH + l];
        float v1 = g_vv[(size_t)j * HH + l + 32];
        float e0 = fmaxf(u0 + v0, 0.f);
        float e1 = fmaxf(u1 + v1, 0.f);
        __syncwarp();
        es[w][l] = e0; es[w][l + 32] = e1;
        __syncwarp();

        float a0 = 0.f, a1 = 0.f;
#pragma unroll
        for (int c4 = 0; c4 < 16; ++c4) {
            float4 ev = ((const float4*)es[w])[c4];
            float2 r;
            r = ((const float2*)(w2s + (c4 * 4 + 0) * HH))[l];
            a0 = fmaf(ev.x, r.x, a0); a1 = fmaf(ev.x, r.y, a1);
            r = ((const float2*)(w2s + (c4 * 4 + 1) * HH))[l];
            a0 = fmaf(ev.y, r.x, a0); a1 = fmaf(ev.y, r.y, a1);
            r = ((const float2*)(w2s + (c4 * 4 + 2) * HH))[l];
            a0 = fmaf(ev.z, r.x, a0); a1 = fmaf(ev.z, r.y, a1);
            r = ((const float2*)(w2s + (c4 * 4 + 3) * HH))[l];
            a0 = fmaf(ev.w, r.x, a0); a1 = fmaf(ev.w, r.y, a1);
        }
        mx0 = fmaxf(mx0, a0); mx1 = fmaxf(mx1, a1);
    }

    ((float2*)(out + (size_t)i * HH))[l] =
        make_float2(mx0 + b2s[2 * l], mx1 + b2s[2 * l + 1]);
}

// =============================================================================
// launch — ordered so the 4th launch (ncu's capture slot) is knn64.
// =============================================================================
extern "C" void kernel_launch(void* const* d_in, const int* in_sizes, int n_in,
                              void* d_out, int out_size) {
    const float* x   = (const float*)d_in[0];
    // d_in[1] = batch (int64) — layout fixed (B=8 contiguous blocks of 4096)
    const float* W1a = (const float*)d_in[2];
    const float* b1a = (const float*)d_in[3];
    const float* W2a = (const float*)d_in[4];
    const float* b2a = (const float*)d_in[5];
    const float* W1b = (const float*)d_in[6];
    const float* b1b = (const float*)d_in[7];
    const float* W2b = (const float*)d_in[8];
    const float* b2b = (const float*)d_in[9];
    float* out = (float*)d_out;

    const int smem_knn3  = 4 * JRANGE * (int)sizeof(float);       // 32 KB
    const int smem_knn64 = (TJ * HH + TJ) * (int)sizeof(float);   // ~130 KB
    cudaFuncSetAttribute(knn3_kernel,
                         cudaFuncAttributeMaxDynamicSharedMemorySize, smem_knn3);
    cudaFuncSetAttribute(knn64_kernel,
                         cudaFuncAttributeMaxDynamicSharedMemorySize, smem_knn64);

    knn3_kernel<<<BB * 16 * JSPLIT, 256, smem_knn3>>>(x);   // 1
    knn_merge_kernel<<<BB * NN / 256, 256>>>();             // 2
    ec1_kernel<<<BB * NN / 8, 256>>>(x, W1a, b1a, W2a, b2a);// 3
    knn64_kernel<<<BB * QT * JSPLIT, 256, smem_knn64>>>();  // 4  <- profiled
    pre2_kernel<<<BB * NN / 8, 256>>>(W1b, b1b);            // 5 (indep of 4)
    knn_merge_kernel<<<BB * NN / 256, 256>>>();             // 6
    ec2_kernel<<<BB * NN / 8, 256>>>(W2b, b2b, out);        // 7
}